// round 5
// baseline (speedup 1.0000x reference)
#include <cuda_runtime.h>
#include <cstdint>
#include <cstddef>
#include <math.h>

#define SEQ   2048
#define BATCH 8
#define DIN   1024
#define DQK   128
#define NG    32
#define NQT   16     // q-tiles per batch

#define SQt 128   // queries per attention block
#define SKt 64    // keys per tile
#define QTS 132   // Qt row stride (d-major)
#define KTS 68    // Kt row stride (d-major)
#define VS_ 132   // Vs / Pt row stride

#define NEG_INF (__int_as_float(0xff800000))

// Scratch (device globals: no allocation allowed)
__device__ float g_proj[3][(size_t)BATCH * SEQ * DQK];
__device__ float g_po[2][BATCH][NQT][SQt][DQK];   // partial O
__device__ float g_pm[2][BATCH][NQT][SQt];        // partial m
__device__ float g_pl[2][BATCH][NQT][SQt];        // partial l

struct InArgs { const float* X[3]; const float* W[3]; const float* B[3]; };
struct GIdx   { int g[NG]; };

// ---------------------------------------------------------------------------
// Projection GEMM: Out[m, j] = sum_d X[m, d] * W[j, d] + b[j]
// ---------------------------------------------------------------------------
__global__ __launch_bounds__(256) void proj_kernel(InArgs in) {
    const int which = blockIdx.y;
    const float* __restrict__ X    = in.X[which];
    const float* __restrict__ W    = in.W[which];
    const float* __restrict__ bias = in.B[which];
    float* __restrict__ Out = g_proj[which];

    const int M0 = blockIdx.x * 128;
    __shared__ float As[8][128];
    __shared__ float Bs[8][128];

    const int tid = threadIdx.x;
    const int ty = tid >> 4, tx = tid & 15;
    const int lr = tid >> 1;
    const int lc = (tid & 1) * 4;

    float acc[8][8];
#pragma unroll
    for (int i = 0; i < 8; i++)
#pragma unroll
        for (int j = 0; j < 8; j++) acc[i][j] = 0.f;

    const float* Xp = X + (size_t)(M0 + lr) * DIN + lc;
    const float* Wp = W + (size_t)lr * DIN + lc;

    for (int k0 = 0; k0 < DIN; k0 += 8) {
        float4 av = *(const float4*)(Xp + k0);
        float4 bv = *(const float4*)(Wp + k0);
        As[lc + 0][lr] = av.x; As[lc + 1][lr] = av.y;
        As[lc + 2][lr] = av.z; As[lc + 3][lr] = av.w;
        Bs[lc + 0][lr] = bv.x; Bs[lc + 1][lr] = bv.y;
        Bs[lc + 2][lr] = bv.z; Bs[lc + 3][lr] = bv.w;
        __syncthreads();
#pragma unroll
        for (int kk = 0; kk < 8; kk++) {
            float a[8], b[8];
            *(float4*)(a)     = *(const float4*)&As[kk][ty * 8];
            *(float4*)(a + 4) = *(const float4*)&As[kk][ty * 8 + 4];
            *(float4*)(b)     = *(const float4*)&Bs[kk][tx * 8];
            *(float4*)(b + 4) = *(const float4*)&Bs[kk][tx * 8 + 4];
#pragma unroll
            for (int i = 0; i < 8; i++)
#pragma unroll
                for (int j = 0; j < 8; j++)
                    acc[i][j] = fmaf(a[i], b[j], acc[i][j]);
        }
        __syncthreads();
    }

    float bb[8];
    *(float4*)(bb)     = *(const float4*)&bias[tx * 8];
    *(float4*)(bb + 4) = *(const float4*)&bias[tx * 8 + 4];
#pragma unroll
    for (int i = 0; i < 8; i++) {
        float4 o0 = make_float4(acc[i][0] + bb[0], acc[i][1] + bb[1],
                                acc[i][2] + bb[2], acc[i][3] + bb[3]);
        float4 o1 = make_float4(acc[i][4] + bb[4], acc[i][5] + bb[5],
                                acc[i][6] + bb[6], acc[i][7] + bb[7]);
        float* op = Out + (size_t)(M0 + ty * 8 + i) * DQK + tx * 8;
        *(float4*)op       = o0;
        *(float4*)(op + 4) = o1;
    }
}

// ---------------------------------------------------------------------------
// Causal attention, split-K over k-tiles (2 CTAs per q-tile), strict k<=q mask.
// Split 1 additionally processes the gathered 32 global-k columns (k>q only).
// Writes partial (m, l, O) states to global scratch.
// ---------------------------------------------------------------------------
__global__ __launch_bounds__(256) void attn_split_kernel(GIdx gt) {
    extern __shared__ float sm[];
    float* Qt = sm;                     // [128 d][132]
    float* Kt = Qt + 128 * QTS;         // [128 d][68]
    float* Vs = Kt + 128 * KTS;         // [64 k][132]
    float* Pt = Vs + SKt * VS_;         // [64 k][132]
    __shared__ int gs[NG];

    const int b  = blockIdx.y;
    const int qt = (NQT - 1) - (blockIdx.x >> 1);  // long CTAs first
    const int sp = blockIdx.x & 1;
    const int q0 = qt * SQt;
    const int tid = threadIdx.x;
    const int ty = tid >> 4, tx = tid & 15;

    const float* Qb = g_proj[0] + (size_t)b * SEQ * DQK;
    const float* Kb = g_proj[1] + (size_t)b * SEQ * DQK;
    const float* Vb = g_proj[2] + (size_t)b * SEQ * DQK;

    if (tid < NG) gs[tid] = gt.g[tid];

    const float inv_scale = 0.08838834764831845f;  // 1/sqrt(128)
    for (int i = tid; i < SQt * 32; i += 256) {
        int row = i >> 5; int d4 = (i & 31) << 2;
        float4 v = *(const float4*)(Qb + (size_t)(q0 + row) * DQK + d4);
        Qt[(d4 + 0) * QTS + row] = v.x * inv_scale;
        Qt[(d4 + 1) * QTS + row] = v.y * inv_scale;
        Qt[(d4 + 2) * QTS + row] = v.z * inv_scale;
        Qt[(d4 + 3) * QTS + row] = v.w * inv_scale;
    }
    __syncthreads();

    float m_i[8], l_i[8], o[8][8];
#pragma unroll
    for (int r = 0; r < 8; r++) {
        m_i[r] = NEG_INF; l_i[r] = 0.f;
#pragma unroll
        for (int c = 0; c < 8; c++) o[r][c] = 0.f;
    }

    // ---- causal tiles: j = sp, sp+2, ..., <= 2*qt+1 ----
    for (int j = sp; j <= 2 * qt + 1; j += 2) {
        const int k0 = j * SKt;
        __syncthreads();
        for (int i = tid; i < SKt * 32; i += 256) {
            int row = i >> 5; int d4 = (i & 31) << 2;
            float4 kv = *(const float4*)(Kb + (size_t)(k0 + row) * DQK + d4);
            Kt[(d4 + 0) * KTS + row] = kv.x;
            Kt[(d4 + 1) * KTS + row] = kv.y;
            Kt[(d4 + 2) * KTS + row] = kv.z;
            Kt[(d4 + 3) * KTS + row] = kv.w;
            float4 vv = *(const float4*)(Vb + (size_t)(k0 + row) * DQK + d4);
            *(float4*)&Vs[row * VS_ + d4] = vv;
        }
        __syncthreads();

        float s[8][4];
#pragma unroll
        for (int r = 0; r < 8; r++) { s[r][0] = s[r][1] = s[r][2] = s[r][3] = 0.f; }
#pragma unroll 4
        for (int d = 0; d < DQK; d++) {
            float4 kc = *(const float4*)&Kt[d * KTS + tx * 4];
            float a[8];
            *(float4*)(a)     = *(const float4*)&Qt[d * QTS + ty * 8];
            *(float4*)(a + 4) = *(const float4*)&Qt[d * QTS + ty * 8 + 4];
#pragma unroll
            for (int r = 0; r < 8; r++) {
                s[r][0] = fmaf(a[r], kc.x, s[r][0]);
                s[r][1] = fmaf(a[r], kc.y, s[r][1]);
                s[r][2] = fmaf(a[r], kc.z, s[r][2]);
                s[r][3] = fmaf(a[r], kc.w, s[r][3]);
            }
        }

        // strict causal mask (k > q -> -inf); only diagonal-adjacent tiles need it
        if (k0 + SKt - 1 > q0) {
#pragma unroll
            for (int r = 0; r < 8; r++) {
                int q = q0 + ty * 8 + r;
#pragma unroll
                for (int c = 0; c < 4; c++) {
                    int k = k0 + tx * 4 + c;
                    if (k > q) s[r][c] = NEG_INF;
                }
            }
        }

#pragma unroll
        for (int r = 0; r < 8; r++) {
            float tm = fmaxf(fmaxf(s[r][0], s[r][1]), fmaxf(s[r][2], s[r][3]));
            tm = fmaxf(tm, __shfl_xor_sync(0xffffffffu, tm, 1, 16));
            tm = fmaxf(tm, __shfl_xor_sync(0xffffffffu, tm, 2, 16));
            tm = fmaxf(tm, __shfl_xor_sync(0xffffffffu, tm, 4, 16));
            tm = fmaxf(tm, __shfl_xor_sync(0xffffffffu, tm, 8, 16));
            float mn = fmaxf(m_i[r], tm);
            float p0, p1, p2, p3;
            if (mn == NEG_INF) {  // fully masked row in this tile: no-op
                p0 = p1 = p2 = p3 = 0.f;
            } else {
                float scl = __expf(m_i[r] - mn);
                p0 = __expf(s[r][0] - mn);
                p1 = __expf(s[r][1] - mn);
                p2 = __expf(s[r][2] - mn);
                p3 = __expf(s[r][3] - mn);
                float rs = p0 + p1 + p2 + p3;
                rs += __shfl_xor_sync(0xffffffffu, rs, 1, 16);
                rs += __shfl_xor_sync(0xffffffffu, rs, 2, 16);
                rs += __shfl_xor_sync(0xffffffffu, rs, 4, 16);
                rs += __shfl_xor_sync(0xffffffffu, rs, 8, 16);
                l_i[r] = l_i[r] * scl + rs;
                m_i[r] = mn;
#pragma unroll
                for (int c = 0; c < 8; c++) o[r][c] *= scl;
            }
            int rowi = ty * 8 + r;
            Pt[(tx * 4 + 0) * VS_ + rowi] = p0;
            Pt[(tx * 4 + 1) * VS_ + rowi] = p1;
            Pt[(tx * 4 + 2) * VS_ + rowi] = p2;
            Pt[(tx * 4 + 3) * VS_ + rowi] = p3;
        }
        __syncthreads();

#pragma unroll 2
        for (int kk = 0; kk < SKt; kk++) {
            float p[8];
            *(float4*)(p)     = *(const float4*)&Pt[kk * VS_ + ty * 8];
            *(float4*)(p + 4) = *(const float4*)&Pt[kk * VS_ + ty * 8 + 4];
            float vv[8];
#pragma unroll
            for (int c = 0; c < 8; c++) vv[c] = Vs[kk * VS_ + c * 16 + tx];
#pragma unroll
            for (int r = 0; r < 8; r++)
#pragma unroll
                for (int c = 0; c < 8; c++)
                    o[r][c] = fmaf(p[r], vv[c], o[r][c]);
        }
    }

    // ---- gathered global-k tile (split 1 only): 32 cols, mask k > q ----
    if (sp == 1) {
        __syncthreads();
        for (int i = tid; i < NG * 32; i += 256) {
            int t = i & 31; int d4 = (i >> 5) << 2;
            int gk = gs[t];
            float4 kv = *(const float4*)(Kb + (size_t)gk * DQK + d4);
            Kt[(d4 + 0) * KTS + t] = kv.x;
            Kt[(d4 + 1) * KTS + t] = kv.y;
            Kt[(d4 + 2) * KTS + t] = kv.z;
            Kt[(d4 + 3) * KTS + t] = kv.w;
            float4 vv = *(const float4*)(Vb + (size_t)gk * DQK + d4);
            *(float4*)&Vs[t * VS_ + d4] = vv;
        }
        __syncthreads();

        float s2[8][2];
#pragma unroll
        for (int r = 0; r < 8; r++) { s2[r][0] = s2[r][1] = 0.f; }
#pragma unroll 4
        for (int d = 0; d < DQK; d++) {
            float2 kc = *(const float2*)&Kt[d * KTS + tx * 2];
            float a[8];
            *(float4*)(a)     = *(const float4*)&Qt[d * QTS + ty * 8];
            *(float4*)(a + 4) = *(const float4*)&Qt[d * QTS + ty * 8 + 4];
#pragma unroll
            for (int r = 0; r < 8; r++) {
                s2[r][0] = fmaf(a[r], kc.x, s2[r][0]);
                s2[r][1] = fmaf(a[r], kc.y, s2[r][1]);
            }
        }
        int kg0 = gs[tx * 2 + 0], kg1 = gs[tx * 2 + 1];
#pragma unroll
        for (int r = 0; r < 8; r++) {
            int q = q0 + ty * 8 + r;
            if (kg0 <= q) s2[r][0] = NEG_INF;   // k<=q already in causal part
            if (kg1 <= q) s2[r][1] = NEG_INF;
        }

#pragma unroll
        for (int r = 0; r < 8; r++) {
            float tm = fmaxf(s2[r][0], s2[r][1]);
            tm = fmaxf(tm, __shfl_xor_sync(0xffffffffu, tm, 1, 16));
            tm = fmaxf(tm, __shfl_xor_sync(0xffffffffu, tm, 2, 16));
            tm = fmaxf(tm, __shfl_xor_sync(0xffffffffu, tm, 4, 16));
            tm = fmaxf(tm, __shfl_xor_sync(0xffffffffu, tm, 8, 16));
            float mn = fmaxf(m_i[r], tm);
            float p0, p1;
            if (mn == NEG_INF) {
                p0 = p1 = 0.f;
            } else {
                float scl = __expf(m_i[r] - mn);
                p0 = __expf(s2[r][0] - mn);
                p1 = __expf(s2[r][1] - mn);
                float rs = p0 + p1;
                rs += __shfl_xor_sync(0xffffffffu, rs, 1, 16);
                rs += __shfl_xor_sync(0xffffffffu, rs, 2, 16);
                rs += __shfl_xor_sync(0xffffffffu, rs, 4, 16);
                rs += __shfl_xor_sync(0xffffffffu, rs, 8, 16);
                l_i[r] = l_i[r] * scl + rs;
                m_i[r] = mn;
#pragma unroll
                for (int c = 0; c < 8; c++) o[r][c] *= scl;
            }
            int rowi = ty * 8 + r;
            Pt[(tx * 2 + 0) * VS_ + rowi] = p0;
            Pt[(tx * 2 + 1) * VS_ + rowi] = p1;
        }
        __syncthreads();

#pragma unroll 2
        for (int kk = 0; kk < NG; kk++) {
            float p[8];
            *(float4*)(p)     = *(const float4*)&Pt[kk * VS_ + ty * 8];
            *(float4*)(p + 4) = *(const float4*)&Pt[kk * VS_ + ty * 8 + 4];
            float vv[8];
#pragma unroll
            for (int c = 0; c < 8; c++) vv[c] = Vs[kk * VS_ + c * 16 + tx];
#pragma unroll
            for (int r = 0; r < 8; r++)
#pragma unroll
                for (int c = 0; c < 8; c++)
                    o[r][c] = fmaf(p[r], vv[c], o[r][c]);
        }
    }

    // ---- write partial state ----
#pragma unroll
    for (int r = 0; r < 8; r++) {
        int row = ty * 8 + r;
        if (tx == 0) {
            g_pm[sp][b][qt][row] = m_i[r];
            g_pl[sp][b][qt][row] = l_i[r];
        }
#pragma unroll
        for (int c = 0; c < 8; c++)
            g_po[sp][b][qt][row][c * 16 + tx] = o[r][c];
    }
}

// ---------------------------------------------------------------------------
// Merge the two partial softmax states per q-tile and write normalized output.
// ---------------------------------------------------------------------------
__global__ __launch_bounds__(256) void merge_kernel(float* __restrict__ Out) {
    const int b = blockIdx.y, qt = blockIdx.x;
    const int row = threadIdx.x >> 1;
    const int dh = (threadIdx.x & 1) * 64;

    float m0 = g_pm[0][b][qt][row], m1 = g_pm[1][b][qt][row];
    float l0 = g_pl[0][b][qt][row], l1 = g_pl[1][b][qt][row];
    float m = fmaxf(m0, m1);
    float w0 = (m0 == NEG_INF) ? 0.f : __expf(m0 - m);
    float w1 = (m1 == NEG_INF) ? 0.f : __expf(m1 - m);
    float inv = 1.f / (l0 * w0 + l1 * w1);

    const float* o0 = &g_po[0][b][qt][row][dh];
    const float* o1 = &g_po[1][b][qt][row][dh];
    float* op = Out + ((size_t)b * SEQ + qt * SQt + row) * DQK + dh;
#pragma unroll
    for (int d = 0; d < 64; d += 4) {
        float4 a = *(const float4*)(o0 + d);
        float4 c = *(const float4*)(o1 + d);
        float4 r;
        r.x = (a.x * w0 + c.x * w1) * inv;
        r.y = (a.y * w0 + c.y * w1) * inv;
        r.z = (a.z * w0 + c.z * w1) * inv;
        r.w = (a.w * w0 + c.w * w1) * inv;
        *(float4*)(op + d) = r;
    }
}

// ---------------------------------------------------------------------------
// Global-q fixup: global query rows attend to ALL keys (mask row = 0).
// Grid (4, BATCH): CTA = 8 global rows of one batch; warp = one row.
// ---------------------------------------------------------------------------
__global__ __launch_bounds__(256) void gq_kernel(float* __restrict__ Out, GIdx gt) {
    extern __shared__ float sm[];
    float* Qs = sm;                  // [8][128]
    float* Kt = Qs + 8 * 128;        // [128][KTS]
    float* Vs = Kt + 128 * KTS;      // [64][VS_]
    float* Ps = Vs + SKt * VS_;      // [8][64]

    const int b = blockIdx.y;
    const int grp = blockIdx.x;
    const int tid = threadIdx.x;
    const int w = tid >> 5, lane = tid & 31;

    const float* Qb = g_proj[0] + (size_t)b * SEQ * DQK;
    const float* Kb = g_proj[1] + (size_t)b * SEQ * DQK;
    const float* Vb = g_proj[2] + (size_t)b * SEQ * DQK;

    const float inv_scale = 0.08838834764831845f;
    {
        int qrow = gt.g[grp * 8 + w];
        float4 v = *(const float4*)(Qb + (size_t)qrow * DQK + lane * 4);
        v.x *= inv_scale; v.y *= inv_scale; v.z *= inv_scale; v.w *= inv_scale;
        *(float4*)&Qs[w * 128 + lane * 4] = v;
    }

    float m = NEG_INF, l = 0.f, o[4] = {0.f, 0.f, 0.f, 0.f};

    for (int t = 0; t < SEQ / SKt; t++) {
        const int k0 = t * SKt;
        __syncthreads();
        for (int i = tid; i < SKt * 32; i += 256) {
            int row = i >> 5; int d4 = (i & 31) << 2;
            float4 kv = *(const float4*)(Kb + (size_t)(k0 + row) * DQK + d4);
            Kt[(d4 + 0) * KTS + row] = kv.x;
            Kt[(d4 + 1) * KTS + row] = kv.y;
            Kt[(d4 + 2) * KTS + row] = kv.z;
            Kt[(d4 + 3) * KTS + row] = kv.w;
            float4 vv = *(const float4*)(Vb + (size_t)(k0 + row) * DQK + d4);
            *(float4*)&Vs[row * VS_ + d4] = vv;
        }
        __syncthreads();

        float s0 = 0.f, s1 = 0.f;
#pragma unroll 4
        for (int d = 0; d < DQK; d++) {
            float qd = Qs[w * 128 + d];
            s0 = fmaf(qd, Kt[d * KTS + lane], s0);
            s1 = fmaf(qd, Kt[d * KTS + lane + 32], s1);
        }
        float tm = fmaxf(s0, s1);
        tm = fmaxf(tm, __shfl_xor_sync(0xffffffffu, tm, 1));
        tm = fmaxf(tm, __shfl_xor_sync(0xffffffffu, tm, 2));
        tm = fmaxf(tm, __shfl_xor_sync(0xffffffffu, tm, 4));
        tm = fmaxf(tm, __shfl_xor_sync(0xffffffffu, tm, 8));
        tm = fmaxf(tm, __shfl_xor_sync(0xffffffffu, tm, 16));
        float mn = fmaxf(m, tm);
        float scl = __expf(m - mn);
        float p0 = __expf(s0 - mn);
        float p1 = __expf(s1 - mn);
        float rs = p0 + p1;
        rs += __shfl_xor_sync(0xffffffffu, rs, 1);
        rs += __shfl_xor_sync(0xffffffffu, rs, 2);
        rs += __shfl_xor_sync(0xffffffffu, rs, 4);
        rs += __shfl_xor_sync(0xffffffffu, rs, 8);
        rs += __shfl_xor_sync(0xffffffffu, rs, 16);
        l = l * scl + rs;
        m = mn;
#pragma unroll
        for (int c = 0; c < 4; c++) o[c] *= scl;

        Ps[w * 64 + lane]      = p0;
        Ps[w * 64 + lane + 32] = p1;
        __syncwarp();
#pragma unroll 4
        for (int k = 0; k < SKt; k++) {
            float pk = Ps[w * 64 + k];
            o[0] = fmaf(pk, Vs[k * VS_ + lane],      o[0]);
            o[1] = fmaf(pk, Vs[k * VS_ + lane + 32], o[1]);
            o[2] = fmaf(pk, Vs[k * VS_ + lane + 64], o[2]);
            o[3] = fmaf(pk, Vs[k * VS_ + lane + 96], o[3]);
        }
    }

    int qrow = gt.g[grp * 8 + w];
    float invl = 1.f / l;
    float* op = Out + ((size_t)b * SEQ + qrow) * DQK + lane;
    op[0]  = o[0] * invl;
    op[32] = o[1] * invl;
    op[64] = o[2] * invl;
    op[96] = o[3] * invl;
}

// ---------------------------------------------------------------------------
// Host: np.random.default_rng(0).choice(2048, 32, replace=False) — Floyd's
// algorithm with 64-slot linear-probe hash set over Lemire-bounded PCG64 draws.
// ---------------------------------------------------------------------------
typedef uint32_t u32; typedef uint64_t u64; typedef unsigned __int128 u128;

static void compute_gtok(int* out) {
    const u32 XSHIFT = 16;
    u32 pool[4];
    u32 hash_const = 0x43b0d7e5u;
    auto hashmix = [&](u32 value) -> u32 {
        value ^= hash_const;
        hash_const *= 0x931e8875u;
        value *= hash_const;
        value ^= value >> XSHIFT;
        return value;
    };
    auto mixfn = [&](u32 x, u32 y) -> u32 {
        u32 r = x * 0xca01f9ddu - y * 0x4973f715u;
        r ^= r >> XSHIFT;
        return r;
    };
    for (int i = 0; i < 4; i++) pool[i] = hashmix(0u);
    for (int s = 0; s < 4; s++)
        for (int d = 0; d < 4; d++)
            if (s != d) pool[d] = mixfn(pool[d], hashmix(pool[s]));

    u32 st32[8];
    u32 hc = 0x8b51f9ddu;
    for (int i = 0; i < 8; i++) {
        u32 dv = pool[i % 4];
        dv ^= hc;
        hc *= 0x58f38dedu;
        dv *= hc;
        dv ^= dv >> XSHIFT;
        st32[i] = dv;
    }
    u64 val[4];
    for (int i = 0; i < 4; i++)
        val[i] = (u64)st32[2 * i] | ((u64)st32[2 * i + 1] << 32);

    const u128 MUL = ((u128)0x2360ed051fc65da4ULL << 64) | 0x4385df649fccf645ULL;
    u128 initstate = ((u128)val[0] << 64) | val[1];
    u128 initseq   = ((u128)val[2] << 64) | val[3];
    u128 state = 0;
    u128 inc = (initseq << 1) | 1;
    state = state * MUL + inc;
    state += initstate;
    state = state * MUL + inc;

    bool has32 = false; u32 cached = 0;
    auto next64 = [&]() -> u64 {
        state = state * MUL + inc;
        u64 hi = (u64)(state >> 64), lo = (u64)state;
        u64 x = hi ^ lo;
        unsigned rot = (unsigned)(state >> 122);
        return (x >> rot) | (x << ((64u - rot) & 63u));
    };
    auto next32 = [&]() -> u32 {
        if (has32) { has32 = false; return cached; }
        u64 n = next64();
        has32 = true; cached = (u32)(n >> 32);
        return (u32)n;
    };
    auto lemire32 = [&](u32 rng) -> u32 {
        const u32 rng_excl = rng + 1u;
        u64 mm = (u64)next32() * (u64)rng_excl;
        u32 leftover = (u32)mm;
        if (leftover < rng_excl) {
            const u32 threshold = (u32)((0xffffffffu - rng) % rng_excl);
            while (leftover < threshold) {
                mm = (u64)next32() * (u64)rng_excl;
                leftover = (u32)mm;
            }
        }
        return (u32)(mm >> 32);
    };

    const u64 EMPTY = ~(u64)0;
    u64 hash_set[64];
    for (int i = 0; i < 64; i++) hash_set[i] = EMPTY;
    int oi = 0;
    for (u32 j = SEQ - NG; j < SEQ; j++) {
        u64 v = (u64)lemire32(j);
        u64 loc = v & 63u;
        while (hash_set[loc] != EMPTY && hash_set[loc] != v) loc = (loc + 1) & 63u;
        if (hash_set[loc] == EMPTY) {
            hash_set[loc] = v;
            out[oi++] = (int)v;
        } else {
            loc = j & 63u;
            while (hash_set[loc] != EMPTY) loc = (loc + 1) & 63u;
            hash_set[loc] = j;
            out[oi++] = (int)j;
        }
    }
}

// ---------------------------------------------------------------------------
extern "C" void kernel_launch(void* const* d_in, const int* in_sizes, int n_in,
                              void* d_out, int out_size) {
    (void)in_sizes; (void)n_in; (void)out_size;
    InArgs ia;
    ia.X[0] = (const float*)d_in[0];
    ia.X[1] = (const float*)d_in[1];
    ia.X[2] = (const float*)d_in[2];
    ia.W[0] = (const float*)d_in[3];  ia.B[0] = (const float*)d_in[4];
    ia.W[1] = (const float*)d_in[5];  ia.B[1] = (const float*)d_in[6];
    ia.W[2] = (const float*)d_in[7];  ia.B[2] = (const float*)d_in[8];

    GIdx gi;
    compute_gtok(gi.g);

    dim3 pg(BATCH * SEQ / 128, 3);
    proj_kernel<<<pg, 256>>>(ia);

    size_t smem = (size_t)(128 * QTS + 128 * KTS + SKt * VS_ + SKt * VS_) * sizeof(float);
    cudaFuncSetAttribute(attn_split_kernel, cudaFuncAttributeMaxDynamicSharedMemorySize, (int)smem);
    attn_split_kernel<<<dim3(NQT * 2, BATCH), 256, smem>>>(gi);

    merge_kernel<<<dim3(NQT, BATCH), 256>>>((float*)d_out);

    size_t smem_gq = (size_t)(8 * 128 + 128 * KTS + SKt * VS_ + 8 * 64) * sizeof(float);
    cudaFuncSetAttribute(gq_kernel, cudaFuncAttributeMaxDynamicSharedMemorySize, (int)smem_gq);
    gq_kernel<<<dim3(4, BATCH), 256, smem_gq>>>((float*)d_out, gi);
}